// round 11
// baseline (speedup 1.0000x reference)
#include <cuda_runtime.h>

#define VOCAB 10000
#define EMB   16
#define HID   32
#define NCLS  2
#define BATCH 4096
#define SEQ   512

typedef unsigned long long ull;

#define TANH_C 2.885390081777927f   // 2*log2(e): tanh(x) = 1 - 2/(exp2(x*C)+1)

// Prescaled projected embedding: g_projC[t][h] = C * (sum_e emb[t][e]*W_ih[h][e] + b_ih[h] + b_hh[h])
__device__ float g_projC[VOCAB * HID];

__global__ void build_proj_kernel(const float* __restrict__ emb,
                                  const float* __restrict__ W_ih,
                                  const float* __restrict__ b_ih,
                                  const float* __restrict__ b_hh) {
    int t    = blockIdx.x * (blockDim.x >> 5) + (threadIdx.x >> 5);
    int lane = threadIdx.x & 31;
    if (t >= VOCAB) return;
    float acc = __ldg(b_ih + lane) + __ldg(b_hh + lane);
#pragma unroll
    for (int e = 0; e < EMB; e++) {
        acc = fmaf(__ldg(emb + t * EMB + e), __ldg(W_ih + lane * EMB + e), acc);
    }
    g_projC[t * HID + lane] = acc * TANH_C;
}

__device__ __forceinline__ ull pack2(float lo, float hi) {
    ull u;
    asm("mov.b64 %0, {%1, %2};" : "=l"(u) : "f"(lo), "f"(hi));
    return u;
}
__device__ __forceinline__ ull fma2(ull a, ull b, ull c) {
    asm("fma.rn.f32x2 %0, %1, %2, %3;" : "=l"(c) : "l"(a), "l"(b), "l"(c));
    return c;
}
__device__ __forceinline__ ull add2(ull a, ull b) {
    ull c;
    asm("add.rn.f32x2 %0, %1, %2;" : "=l"(c) : "l"(a), "l"(b));
    return c;
}
// 128-bit shared load -> two packed f32x2 operands (volatile: addresses repeat).
__device__ __forceinline__ void lds2(ull& a, ull& b, unsigned addr) {
    asm volatile("ld.shared.v2.u64 {%0, %1}, [%2];" : "=l"(a), "=l"(b) : "r"(addr));
}

// Split-2 layout: lane = (q16 = lane>>1, c1 = lane&1).
//  - owns h-chunk k in [16*c1, 16*c1+16)  (4 LDS.128/step, 64B/lane)
//  - accumulator i (i=0,1) = partial for output row  q16 + 16*(c1^i)  (permuted)
//  - single-stage butterfly (1 shfl + 1 fadd) lands output p = q16+16*c1 here.
//  MIO/step ~= 7 (4 LDS + STS + LDG + 1 SHFL), same as split-4, but 12 fewer
//  scalar ops and one less shfl stage on the serial chain.
__global__ void __launch_bounds__(64, 14) rnn_step_kernel(
    const int* __restrict__ x,
    const float* __restrict__ W_hh,
    const float* __restrict__ W_fc,
    const float* __restrict__ b_fc,
    float* __restrict__ out) {

    int wl   = threadIdx.x >> 5;
    int lane = threadIdx.x & 31;
    int q16  = lane >> 1;
    int c1   = lane & 1;
    int p    = q16 + 16 * c1;        // the output index this lane finalizes
    int b    = blockIdx.x * 2 + wl;

    __shared__ __align__(16) float hbuf[2][2][HID];

    // w2[i*8 + t] pairs with accumulator i: W_hh[q16 + 16*(c1^i)][16*c1 + 2t .. +2).
    ull w2[16];
#pragma unroll
    for (int i = 0; i < 2; i++) {
        const float2* wr = (const float2*)(W_hh + (q16 + 16 * (c1 ^ i)) * HID + 16 * c1);
#pragma unroll
        for (int t = 0; t < 8; t++) {
            float2 wf = __ldg(wr + t);
            w2[i * 8 + t] = pack2(wf.x, wf.y);
        }
    }

    unsigned hb0 = (unsigned)__cvta_generic_to_shared(&hbuf[wl][0][0]) + c1 * 64;
    unsigned hb1 = (unsigned)__cvta_generic_to_shared(&hbuf[wl][1][0]) + c1 * 64;

    const int4* xb4 = (const int4*)(x + b * SEQ);

    hbuf[wl][0][p] = 0.0f;
    float h = 0.0f;

    // Prime the 2-deep proj prefetch pipeline (tokens 0,1).
    int4 tc = __ldg(xb4);
    float xpA = __ldg(&g_projC[tc.x * HID + p]);
    float xpB = __ldg(&g_projC[tc.y * HID + p]);

#define STEP(PAR, XP, TOKPF)                                                   \
    {                                                                          \
        float xuC = (XP);                                                      \
        (XP) = __ldg(&g_projC[(TOKPF) * HID + p]); /* prefetch s+2 */          \
        __syncwarp();                                                          \
        unsigned src = (PAR) ? hb1 : hb0;                                      \
        ull hp0, hp1, hp2, hp3, hp4, hp5, hp6, hp7;                            \
        lds2(hp0, hp1, src);                                                   \
        lds2(hp2, hp3, src + 16);                                              \
        lds2(hp4, hp5, src + 32);                                              \
        lds2(hp6, hp7, src + 48);                                              \
        ull a00 = 0, a01 = 0, a10 = 0, a11 = 0;                                \
        a00 = fma2(hp0, w2[0],  a00); a10 = fma2(hp0, w2[8],  a10);            \
        a01 = fma2(hp1, w2[1],  a01); a11 = fma2(hp1, w2[9],  a11);            \
        a00 = fma2(hp2, w2[2],  a00); a10 = fma2(hp2, w2[10], a10);            \
        a01 = fma2(hp3, w2[3],  a01); a11 = fma2(hp3, w2[11], a11);            \
        a00 = fma2(hp4, w2[4],  a00); a10 = fma2(hp4, w2[12], a10);            \
        a01 = fma2(hp5, w2[5],  a01); a11 = fma2(hp5, w2[13], a11);            \
        a00 = fma2(hp6, w2[6],  a00); a10 = fma2(hp6, w2[14], a10);            \
        a01 = fma2(hp7, w2[7],  a01); a11 = fma2(hp7, w2[15], a11);            \
        ull A0 = add2(a00, a01);                                               \
        ull A1 = add2(a10, a11);                                               \
        float l0, h0, l1, h1;                                                  \
        asm("mov.b64 {%0, %1}, %2;" : "=f"(l0), "=f"(h0) : "l"(A0));           \
        asm("mov.b64 {%0, %1}, %2;" : "=f"(l1), "=f"(h1) : "l"(A1));           \
        float s0 = l0 + h0;                                                    \
        float s1 = l1 + h1;                                                    \
        /* partner lane (c1^1) holds the other half of output p in its s1 */   \
        float v = s0 + __shfl_xor_sync(0xffffffffu, s1, 1);                    \
        float e;                                                               \
        asm("ex2.approx.f32 %0, %1;" : "=f"(e) : "f"(fmaf(v, TANH_C, xuC)));   \
        float r;                                                               \
        asm("rcp.approx.f32 %0, %1;" : "=f"(r) : "f"(e + 1.0f));               \
        h = fmaf(-2.0f, r, 1.0f);                                              \
        hbuf[wl][(PAR) ^ 1][p] = h;                                            \
    }

    for (int g = 0; g < SEQ / 4; g++) {
        int gn = (g + 1 < SEQ / 4) ? g + 1 : g;   // clamp: trailing prefetches discarded
        int4 tn = __ldg(&xb4[gn]);                // one uniform LDG.128 per 4 steps
        STEP(0, xpA, tc.z);   // s = 4g+0, prefetch s+2
        STEP(1, xpB, tc.w);   // s = 4g+1
        STEP(0, xpA, tn.x);   // s = 4g+2
        STEP(1, xpB, tn.y);   // s = 4g+3
        tc = tn;
    }
#undef STEP

    // Classifier head: lane holds h_final[p]; two full-warp reductions.
    float v0 = h * __ldg(W_fc + p);
    float v1 = h * __ldg(W_fc + HID + p);
#pragma unroll
    for (int o = 16; o > 0; o >>= 1) {
        v0 += __shfl_xor_sync(0xffffffffu, v0, o);
        v1 += __shfl_xor_sync(0xffffffffu, v1, o);
    }
    if (lane == 0) {
        out[b * NCLS + 0] = v0 + __ldg(b_fc + 0);
        out[b * NCLS + 1] = v1 + __ldg(b_fc + 1);
    }
}

extern "C" void kernel_launch(void* const* d_in, const int* in_sizes, int n_in,
                              void* d_out, int out_size) {
    const int*   x    = (const int*)d_in[0];
    const float* emb  = (const float*)d_in[1];
    const float* W_ih = (const float*)d_in[2];
    const float* W_hh = (const float*)d_in[3];
    const float* b_ih = (const float*)d_in[4];
    const float* b_hh = (const float*)d_in[5];
    const float* W_fc = (const float*)d_in[6];
    const float* b_fc = (const float*)d_in[7];
    float* out = (float*)d_out;

    build_proj_kernel<<<(VOCAB + 7) / 8, 256>>>(emb, W_ih, b_ih, b_hh);
    rnn_step_kernel<<<BATCH / 2, 64>>>(x, W_hh, W_fc, b_fc, out);
}

// round 12
// speedup vs baseline: 1.0778x; 1.0778x over previous
#include <cuda_runtime.h>

#define VOCAB 10000
#define EMB   16
#define HID   32
#define NCLS  2
#define BATCH 4096
#define SEQ   512

typedef unsigned long long ull;

#define TANH_C 2.885390081777927f   // 2*log2(e): tanh(x) = 1 - 2/(exp2(x*C)+1)

// Prescaled projected embedding: g_projC[t][h] = C * (sum_e emb[t][e]*W_ih[h][e] + b_ih[h] + b_hh[h])
__device__ float g_projC[VOCAB * HID];

__global__ void build_proj_kernel(const float* __restrict__ emb,
                                  const float* __restrict__ W_ih,
                                  const float* __restrict__ b_ih,
                                  const float* __restrict__ b_hh) {
    int t    = blockIdx.x * (blockDim.x >> 5) + (threadIdx.x >> 5);
    int lane = threadIdx.x & 31;
    if (t >= VOCAB) return;
    float acc = __ldg(b_ih + lane) + __ldg(b_hh + lane);
#pragma unroll
    for (int e = 0; e < EMB; e++) {
        acc = fmaf(__ldg(emb + t * EMB + e), __ldg(W_ih + lane * EMB + e), acc);
    }
    g_projC[t * HID + lane] = acc * TANH_C;
}

__device__ __forceinline__ ull pack2(float lo, float hi) {
    ull u;
    asm("mov.b64 %0, {%1, %2};" : "=l"(u) : "f"(lo), "f"(hi));
    return u;
}
__device__ __forceinline__ ull fma2(ull a, ull b, ull c) {
    asm("fma.rn.f32x2 %0, %1, %2, %3;" : "=l"(c) : "l"(a), "l"(b), "l"(c));
    return c;
}
// 128-bit shared load -> two packed f32x2 operands (volatile: addresses repeat).
__device__ __forceinline__ void lds2(ull& a, ull& b, unsigned addr) {
    asm volatile("ld.shared.v2.u64 {%0, %1}, [%2];" : "=l"(a), "=l"(b) : "r"(addr));
}

// Split-4 layout: lane = (q = lane>>2, c = lane&3).
//  - owns h-chunk k in [8c, 8c+8)  (2 LDS.128/step)
//  - accumulator i = partial for output row  q + 8*(c^i)   (permuted)
//  - FLAT reduce: lane c^j holds partial j for output p in its s_j, so
//    v = s0 + shfl(s1,1) + shfl(s2,2) + shfl(s3,3) — 3 INDEPENDENT shfls,
//    one latency stage instead of two. Same ops, same summation order.
__global__ void __launch_bounds__(64, 14) rnn_step_kernel(
    const int* __restrict__ x,
    const float* __restrict__ W_hh,
    const float* __restrict__ W_fc,
    const float* __restrict__ b_fc,
    float* __restrict__ out) {

    int wl   = threadIdx.x >> 5;
    int lane = threadIdx.x & 31;
    int q    = lane >> 2;
    int c    = lane & 3;
    int p    = q + 8 * c;            // the output index this lane finalizes
    int b    = blockIdx.x * 2 + wl;

    __shared__ __align__(16) float hbuf[2][2][HID];

    // w2[i*4 + t] pairs with accumulator i: W_hh[q + 8*(c^i)][8c + 2t .. +2).
    ull w2[16];
#pragma unroll
    for (int i = 0; i < 4; i++) {
        const float2* wr = (const float2*)(W_hh + (q + 8 * (c ^ i)) * HID + 8 * c);
#pragma unroll
        for (int t = 0; t < 4; t++) {
            float2 wf = __ldg(wr + t);
            w2[i * 4 + t] = pack2(wf.x, wf.y);
        }
    }

    unsigned base0 = (unsigned)__cvta_generic_to_shared(&hbuf[wl][0][0]);
    unsigned base1 = (unsigned)__cvta_generic_to_shared(&hbuf[wl][1][0]);
    unsigned hb0 = base0 + c * 32;        // load address (own k-chunk) in buf0
    unsigned hb1 = base1 + c * 32;        // ... in buf1
    unsigned stA = base0 + p * 4;         // store address for h[p] in buf0
    unsigned stB = base1 + p * 4;         // ... in buf1

    const int4* xb4 = (const int4*)(x + b * SEQ);

    hbuf[wl][0][lane] = 0.0f;
    float h = 0.0f;

    // Prime the 2-deep proj prefetch pipeline (tokens 0,1).
    int4 tc = __ldg(xb4);
    float xpA = __ldg(&g_projC[tc.x * HID + p]);
    float xpB = __ldg(&g_projC[tc.y * HID + p]);

#define STEP(PAR, XP, TOKPF)                                                   \
    {                                                                          \
        float xuC = (XP);                                                      \
        (XP) = __ldg(&g_projC[(TOKPF) * HID + p]); /* prefetch s+2 */          \
        __syncwarp();                                                          \
        unsigned src = (PAR) ? hb1 : hb0;                                      \
        ull hp0, hp1, hp2, hp3;                                                \
        lds2(hp0, hp1, src);                                                   \
        lds2(hp2, hp3, src + 16);                                              \
        ull a0 = 0, a1 = 0, a2 = 0, a3 = 0;                                    \
        a0 = fma2(hp0, w2[0],  a0); a1 = fma2(hp0, w2[4],  a1);                \
        a2 = fma2(hp0, w2[8],  a2); a3 = fma2(hp0, w2[12], a3);                \
        a0 = fma2(hp1, w2[1],  a0); a1 = fma2(hp1, w2[5],  a1);                \
        a2 = fma2(hp1, w2[9],  a2); a3 = fma2(hp1, w2[13], a3);                \
        a0 = fma2(hp2, w2[2],  a0); a1 = fma2(hp2, w2[6],  a1);                \
        a2 = fma2(hp2, w2[10], a2); a3 = fma2(hp2, w2[14], a3);                \
        a0 = fma2(hp3, w2[3],  a0); a1 = fma2(hp3, w2[7],  a1);                \
        a2 = fma2(hp3, w2[11], a2); a3 = fma2(hp3, w2[15], a3);                \
        float l0, h0, l1, h1, l2, h2, l3, h3;                                  \
        asm("mov.b64 {%0, %1}, %2;" : "=f"(l0), "=f"(h0) : "l"(a0));           \
        asm("mov.b64 {%0, %1}, %2;" : "=f"(l1), "=f"(h1) : "l"(a1));           \
        asm("mov.b64 {%0, %1}, %2;" : "=f"(l2), "=f"(h2) : "l"(a2));           \
        asm("mov.b64 {%0, %1}, %2;" : "=f"(l3), "=f"(h3) : "l"(a3));           \
        float s0 = l0 + h0, s1 = l1 + h1, s2 = l2 + h2, s3 = l3 + h3;          \
        /* flat permuted reduce: 3 independent shfls, one latency stage */     \
        float t1 = __shfl_xor_sync(0xffffffffu, s1, 1);                        \
        float t2 = __shfl_xor_sync(0xffffffffu, s2, 2);                        \
        float t3 = __shfl_xor_sync(0xffffffffu, s3, 3);                        \
        float v  = (s0 + t1) + (t2 + t3);                                      \
        float e;                                                               \
        asm("ex2.approx.f32 %0, %1;" : "=f"(e) : "f"(fmaf(v, TANH_C, xuC)));   \
        float r;                                                               \
        asm("rcp.approx.f32 %0, %1;" : "=f"(r) : "f"(e + 1.0f));               \
        h = fmaf(-2.0f, r, 1.0f);                                              \
        asm volatile("st.shared.f32 [%0], %1;"                                 \
                     :: "r"((PAR) ? stA : stB), "f"(h) : "memory");            \
    }

    for (int g = 0; g < SEQ / 4 - 1; g++) {
        int4 tn = __ldg(&xb4[g + 1]);             // one uniform LDG.128 per 4 steps
        STEP(0, xpA, tc.z);   // s = 4g+0, prefetch s+2
        STEP(1, xpB, tc.w);   // s = 4g+1
        STEP(0, xpA, tn.x);   // s = 4g+2
        STEP(1, xpB, tn.y);   // s = 4g+3
        tc = tn;
    }
    // Final group (g = 127): trailing prefetches reuse current tokens (discarded).
    STEP(0, xpA, tc.z);
    STEP(1, xpB, tc.w);
    STEP(0, xpA, tc.x);
    STEP(1, xpB, tc.y);
#undef STEP

    // Classifier head: lane holds h_final[p]; two full-warp reductions.
    float v0 = h * __ldg(W_fc + p);
    float v1 = h * __ldg(W_fc + HID + p);
#pragma unroll
    for (int o = 16; o > 0; o >>= 1) {
        v0 += __shfl_xor_sync(0xffffffffu, v0, o);
        v1 += __shfl_xor_sync(0xffffffffu, v1, o);
    }
    if (lane == 0) {
        out[b * NCLS + 0] = v0 + __ldg(b_fc + 0);
        out[b * NCLS + 1] = v1 + __ldg(b_fc + 1);
    }
}

extern "C" void kernel_launch(void* const* d_in, const int* in_sizes, int n_in,
                              void* d_out, int out_size) {
    const int*   x    = (const int*)d_in[0];
    const float* emb  = (const float*)d_in[1];
    const float* W_ih = (const float*)d_in[2];
    const float* W_hh = (const float*)d_in[3];
    const float* b_ih = (const float*)d_in[4];
    const float* b_hh = (const float*)d_in[5];
    const float* W_fc = (const float*)d_in[6];
    const float* b_fc = (const float*)d_in[7];
    float* out = (float*)d_out;

    build_proj_kernel<<<(VOCAB + 7) / 8, 256>>>(emb, W_ih, b_ih, b_hh);
    rnn_step_kernel<<<BATCH / 2, 64>>>(x, W_hh, W_fc, b_fc, out);
}

// round 13
// speedup vs baseline: 1.2858x; 1.1930x over previous
#include <cuda_runtime.h>

#define VOCAB 10000
#define EMB   16
#define HID   32
#define NCLS  2
#define BATCH 4096
#define SEQ   512

typedef unsigned long long ull;

// Projected embedding table: proj[t][h] = sum_e emb[t][e]*W_ih[h][e] + b_ih[h] + b_hh[h]
__device__ float g_proj[VOCAB * HID];

__global__ void build_proj_kernel(const float* __restrict__ emb,
                                  const float* __restrict__ W_ih,
                                  const float* __restrict__ b_ih,
                                  const float* __restrict__ b_hh) {
    int t    = blockIdx.x * (blockDim.x >> 5) + (threadIdx.x >> 5);
    int lane = threadIdx.x & 31;
    if (t >= VOCAB) return;
    float acc = __ldg(b_ih + lane) + __ldg(b_hh + lane);
#pragma unroll
    for (int e = 0; e < EMB; e++) {
        acc = fmaf(__ldg(emb + t * EMB + e), __ldg(W_ih + lane * EMB + e), acc);
    }
    g_proj[t * HID + lane] = acc;
}

__device__ __forceinline__ ull pack2(float lo, float hi) {
    ull u;
    asm("mov.b64 %0, {%1, %2};" : "=l"(u) : "f"(lo), "f"(hi));
    return u;
}
__device__ __forceinline__ ull fma2(ull a, ull b, ull c) {
    asm("fma.rn.f32x2 %0, %1, %2, %3;" : "=l"(c) : "l"(a), "l"(b), "l"(c));
    return c;
}
// 128-bit shared load -> two packed f32x2 operands (volatile: addresses repeat).
__device__ __forceinline__ void lds2(ull& a, ull& b, unsigned addr) {
    asm volatile("ld.shared.v2.u64 {%0, %1}, [%2];" : "=l"(a), "=l"(b) : "r"(addr));
}

// Split-4 layout: lane = (q = lane>>2, c = lane&3).
//  - owns h-chunk k in [8c, 8c+8)  (2 LDS.128/step)
//  - accumulator i = partial for output row  q + 8*(c^i)   (permuted)
//  - FLAT reduce (3 independent shfls, one latency stage)
//  - HW tanh.approx.f32: one MUFU replaces the 5-op ex2/rcp block (-28 cy chain)
__global__ void __launch_bounds__(64, 14) rnn_step_kernel(
    const int* __restrict__ x,
    const float* __restrict__ W_hh,
    const float* __restrict__ W_fc,
    const float* __restrict__ b_fc,
    float* __restrict__ out) {

    int wl   = threadIdx.x >> 5;
    int lane = threadIdx.x & 31;
    int q    = lane >> 2;
    int c    = lane & 3;
    int p    = q + 8 * c;            // the output index this lane finalizes
    int b    = blockIdx.x * 2 + wl;

    __shared__ __align__(16) float hbuf[2][2][HID];

    // w2[i*4 + t] pairs with accumulator i: W_hh[q + 8*(c^i)][8c + 2t .. +2).
    ull w2[16];
#pragma unroll
    for (int i = 0; i < 4; i++) {
        const float2* wr = (const float2*)(W_hh + (q + 8 * (c ^ i)) * HID + 8 * c);
#pragma unroll
        for (int t = 0; t < 4; t++) {
            float2 wf = __ldg(wr + t);
            w2[i * 4 + t] = pack2(wf.x, wf.y);
        }
    }

    unsigned base0 = (unsigned)__cvta_generic_to_shared(&hbuf[wl][0][0]);
    unsigned base1 = (unsigned)__cvta_generic_to_shared(&hbuf[wl][1][0]);
    unsigned hb0 = base0 + c * 32;        // load address (own k-chunk) in buf0
    unsigned hb1 = base1 + c * 32;        // ... in buf1
    unsigned stA = base0 + p * 4;         // store address for h[p] in buf0
    unsigned stB = base1 + p * 4;         // ... in buf1

    const int4* xb4 = (const int4*)(x + b * SEQ);

    hbuf[wl][0][lane] = 0.0f;
    float h = 0.0f;

    // Prime the 2-deep proj prefetch pipeline (tokens 0,1).
    int4 tc = __ldg(xb4);
    float xpA = __ldg(&g_proj[tc.x * HID + p]);
    float xpB = __ldg(&g_proj[tc.y * HID + p]);

#define STEP(PAR, XP, TOKPF)                                                   \
    {                                                                          \
        float xu = (XP);                                                       \
        (XP) = __ldg(&g_proj[(TOKPF) * HID + p]); /* prefetch s+2 */           \
        __syncwarp();                                                          \
        unsigned src = (PAR) ? hb1 : hb0;                                      \
        ull hp0, hp1, hp2, hp3;                                                \
        lds2(hp0, hp1, src);                                                   \
        lds2(hp2, hp3, src + 16);                                              \
        ull a0 = 0, a1 = 0, a2 = 0, a3 = 0;                                    \
        a0 = fma2(hp0, w2[0],  a0); a1 = fma2(hp0, w2[4],  a1);                \
        a2 = fma2(hp0, w2[8],  a2); a3 = fma2(hp0, w2[12], a3);                \
        a0 = fma2(hp1, w2[1],  a0); a1 = fma2(hp1, w2[5],  a1);                \
        a2 = fma2(hp1, w2[9],  a2); a3 = fma2(hp1, w2[13], a3);                \
        a0 = fma2(hp2, w2[2],  a0); a1 = fma2(hp2, w2[6],  a1);                \
        a2 = fma2(hp2, w2[10], a2); a3 = fma2(hp2, w2[14], a3);                \
        a0 = fma2(hp3, w2[3],  a0); a1 = fma2(hp3, w2[7],  a1);                \
        a2 = fma2(hp3, w2[11], a2); a3 = fma2(hp3, w2[15], a3);                \
        float l0, h0, l1, h1, l2, h2, l3, h3;                                  \
        asm("mov.b64 {%0, %1}, %2;" : "=f"(l0), "=f"(h0) : "l"(a0));           \
        asm("mov.b64 {%0, %1}, %2;" : "=f"(l1), "=f"(h1) : "l"(a1));           \
        asm("mov.b64 {%0, %1}, %2;" : "=f"(l2), "=f"(h2) : "l"(a2));           \
        asm("mov.b64 {%0, %1}, %2;" : "=f"(l3), "=f"(h3) : "l"(a3));           \
        float s0 = l0 + h0, s1 = l1 + h1, s2 = l2 + h2, s3 = l3 + h3;          \
        /* flat permuted reduce: 3 independent shfls, one latency stage */     \
        float t1 = __shfl_xor_sync(0xffffffffu, s1, 1);                        \
        float t2 = __shfl_xor_sync(0xffffffffu, s2, 2);                        \
        float t3 = __shfl_xor_sync(0xffffffffu, s3, 3);                        \
        float v  = (s0 + t1) + (t2 + t3);                                      \
        asm("tanh.approx.f32 %0, %1;" : "=f"(h) : "f"(v + xu));                \
        asm volatile("st.shared.f32 [%0], %1;"                                 \
                     :: "r"((PAR) ? stA : stB), "f"(h) : "memory");            \
    }

    for (int g = 0; g < SEQ / 4 - 1; g++) {
        int4 tn = __ldg(&xb4[g + 1]);             // one uniform LDG.128 per 4 steps
        STEP(0, xpA, tc.z);   // s = 4g+0, prefetch s+2
        STEP(1, xpB, tc.w);   // s = 4g+1
        STEP(0, xpA, tn.x);   // s = 4g+2
        STEP(1, xpB, tn.y);   // s = 4g+3
        tc = tn;
    }
    // Final group (g = 127): trailing prefetches reuse current tokens (discarded).
    STEP(0, xpA, tc.z);
    STEP(1, xpB, tc.w);
    STEP(0, xpA, tc.x);
    STEP(1, xpB, tc.y);
#undef STEP

    // Classifier head: lane holds h_final[p]; two full-warp reductions.
    float v0 = h * __ldg(W_fc + p);
    float v1 = h * __ldg(W_fc + HID + p);
#pragma unroll
    for (int o = 16; o > 0; o >>= 1) {
        v0 += __shfl_xor_sync(0xffffffffu, v0, o);
        v1 += __shfl_xor_sync(0xffffffffu, v1, o);
    }
    if (lane == 0) {
        out[b * NCLS + 0] = v0 + __ldg(b_fc + 0);
        out[b * NCLS + 1] = v1 + __ldg(b_fc + 1);
    }
}

extern "C" void kernel_launch(void* const* d_in, const int* in_sizes, int n_in,
                              void* d_out, int out_size) {
    const int*   x    = (const int*)d_in[0];
    const float* emb  = (const float*)d_in[1];
    const float* W_ih = (const float*)d_in[2];
    const float* W_hh = (const float*)d_in[3];
    const float* b_ih = (const float*)d_in[4];
    const float* b_hh = (const float*)d_in[5];
    const float* W_fc = (const float*)d_in[6];
    const float* b_fc = (const float*)d_in[7];
    float* out = (float*)d_out;

    build_proj_kernel<<<(VOCAB + 7) / 8, 256>>>(emb, W_ih, b_ih, b_hh);
    rnn_step_kernel<<<BATCH / 2, 64>>>(x, W_hh, W_fc, b_fc, out);
}

// round 14
// speedup vs baseline: 1.3105x; 1.0192x over previous
#include <cuda_runtime.h>

#define VOCAB 10000
#define EMB   16
#define HID   32
#define NCLS  2
#define BATCH 4096
#define SEQ   512

typedef unsigned long long ull;

// Projected embedding table: proj[t][h] = sum_e emb[t][e]*W_ih[h][e] + b_ih[h] + b_hh[h]
__device__ float g_proj[VOCAB * HID];

__global__ void build_proj_kernel(const float* __restrict__ emb,
                                  const float* __restrict__ W_ih,
                                  const float* __restrict__ b_ih,
                                  const float* __restrict__ b_hh) {
    int t    = blockIdx.x * (blockDim.x >> 5) + (threadIdx.x >> 5);
    int lane = threadIdx.x & 31;
    if (t >= VOCAB) return;
    float acc = __ldg(b_ih + lane) + __ldg(b_hh + lane);
#pragma unroll
    for (int e = 0; e < EMB; e++) {
        acc = fmaf(__ldg(emb + t * EMB + e), __ldg(W_ih + lane * EMB + e), acc);
    }
    g_proj[t * HID + lane] = acc;
}

__device__ __forceinline__ ull pack2(float lo, float hi) {
    ull u;
    asm("mov.b64 %0, {%1, %2};" : "=l"(u) : "f"(lo), "f"(hi));
    return u;
}
__device__ __forceinline__ ull fma2(ull a, ull b, ull c) {
    asm("fma.rn.f32x2 %0, %1, %2, %3;" : "=l"(c) : "l"(a), "l"(b), "l"(c));
    return c;
}
// 128-bit shared load -> two packed f32x2 operands (volatile: addresses repeat).
__device__ __forceinline__ void lds2(ull& a, ull& b, unsigned addr) {
    asm volatile("ld.shared.v2.u64 {%0, %1}, [%2];" : "=l"(a), "=l"(b) : "r"(addr));
}

// Split-4 layout: lane = (q = lane>>2, c = lane&3).
//  - owns h-chunk k in [8c, 8c+8)  (2 LDS.128/step)
//  - accumulator i = partial for output row  q + 8*(c^i)   (permuted)
//  - FLAT reduce (3 independent shfls, one latency stage)
//  - HW tanh.approx.f32 (single MUFU)
//  - NO per-step syncwarp: hbuf is warp-private, the loop is branch-free
//    (no divergence), shfl.sync reconverges every step, and same-warp
//    STS->LDS on shared memory is ordered through the in-order LSU queue.
__global__ void __launch_bounds__(64, 14) rnn_step_kernel(
    const int* __restrict__ x,
    const float* __restrict__ W_hh,
    const float* __restrict__ W_fc,
    const float* __restrict__ b_fc,
    float* __restrict__ out) {

    int wl   = threadIdx.x >> 5;
    int lane = threadIdx.x & 31;
    int q    = lane >> 2;
    int c    = lane & 3;
    int p    = q + 8 * c;            // the output index this lane finalizes
    int b    = blockIdx.x * 2 + wl;

    __shared__ __align__(16) float hbuf[2][2][HID];

    // w2[i*4 + t] pairs with accumulator i: W_hh[q + 8*(c^i)][8c + 2t .. +2).
    ull w2[16];
#pragma unroll
    for (int i = 0; i < 4; i++) {
        const float2* wr = (const float2*)(W_hh + (q + 8 * (c ^ i)) * HID + 8 * c);
#pragma unroll
        for (int t = 0; t < 4; t++) {
            float2 wf = __ldg(wr + t);
            w2[i * 4 + t] = pack2(wf.x, wf.y);
        }
    }

    unsigned base0 = (unsigned)__cvta_generic_to_shared(&hbuf[wl][0][0]);
    unsigned base1 = (unsigned)__cvta_generic_to_shared(&hbuf[wl][1][0]);
    unsigned hb0 = base0 + c * 32;        // load address (own k-chunk) in buf0
    unsigned hb1 = base1 + c * 32;        // ... in buf1
    unsigned stA = base0 + p * 4;         // store address for h[p] in buf0
    unsigned stB = base1 + p * 4;         // ... in buf1

    const int4* xb4 = (const int4*)(x + b * SEQ);

    hbuf[wl][0][lane] = 0.0f;
    __syncwarp();                          // one-time: init visible before loop
    float h = 0.0f;

    // Prime the 2-deep proj prefetch pipeline (tokens 0,1).
    int4 tc = __ldg(xb4);
    float xpA = __ldg(&g_proj[tc.x * HID + p]);
    float xpB = __ldg(&g_proj[tc.y * HID + p]);

#define STEP(PAR, XP, TOKPF)                                                   \
    {                                                                          \
        float xu = (XP);                                                       \
        (XP) = __ldg(&g_proj[(TOKPF) * HID + p]); /* prefetch s+2 */           \
        unsigned src = (PAR) ? hb1 : hb0;                                      \
        ull hp0, hp1, hp2, hp3;                                                \
        lds2(hp0, hp1, src);                                                   \
        lds2(hp2, hp3, src + 16);                                              \
        ull a0 = 0, a1 = 0, a2 = 0, a3 = 0;                                    \
        a0 = fma2(hp0, w2[0],  a0); a1 = fma2(hp0, w2[4],  a1);                \
        a2 = fma2(hp0, w2[8],  a2); a3 = fma2(hp0, w2[12], a3);                \
        a0 = fma2(hp1, w2[1],  a0); a1 = fma2(hp1, w2[5],  a1);                \
        a2 = fma2(hp1, w2[9],  a2); a3 = fma2(hp1, w2[13], a3);                \
        a0 = fma2(hp2, w2[2],  a0); a1 = fma2(hp2, w2[6],  a1);                \
        a2 = fma2(hp2, w2[10], a2); a3 = fma2(hp2, w2[14], a3);                \
        a0 = fma2(hp3, w2[3],  a0); a1 = fma2(hp3, w2[7],  a1);                \
        a2 = fma2(hp3, w2[11], a2); a3 = fma2(hp3, w2[15], a3);                \
        float l0, h0, l1, h1, l2, h2, l3, h3;                                  \
        asm("mov.b64 {%0, %1}, %2;" : "=f"(l0), "=f"(h0) : "l"(a0));           \
        asm("mov.b64 {%0, %1}, %2;" : "=f"(l1), "=f"(h1) : "l"(a1));           \
        asm("mov.b64 {%0, %1}, %2;" : "=f"(l2), "=f"(h2) : "l"(a2));           \
        asm("mov.b64 {%0, %1}, %2;" : "=f"(l3), "=f"(h3) : "l"(a3));           \
        float s1 = l1 + h1, s2 = l2 + h2, s3 = l3 + h3;                        \
        float s0 = (l0 + h0) + xu;  /* xu folded in during shfl flight */      \
        float t1 = __shfl_xor_sync(0xffffffffu, s1, 1);                        \
        float t2 = __shfl_xor_sync(0xffffffffu, s2, 2);                        \
        float t3 = __shfl_xor_sync(0xffffffffu, s3, 3);                        \
        float v  = (s0 + t1) + (t2 + t3);                                      \
        asm("tanh.approx.f32 %0, %1;" : "=f"(h) : "f"(v));                     \
        asm volatile("st.shared.f32 [%0], %1;"                                 \
                     :: "r"((PAR) ? stA : stB), "f"(h) : "memory");            \
    }

    for (int g = 0; g < SEQ / 4 - 1; g++) {
        int4 tn = __ldg(&xb4[g + 1]);             // one uniform LDG.128 per 4 steps
        STEP(0, xpA, tc.z);   // s = 4g+0, prefetch s+2
        STEP(1, xpB, tc.w);   // s = 4g+1
        STEP(0, xpA, tn.x);   // s = 4g+2
        STEP(1, xpB, tn.y);   // s = 4g+3
        tc = tn;
    }
    // Final group (g = 127): trailing prefetches reuse current tokens (discarded).
    STEP(0, xpA, tc.z);
    STEP(1, xpB, tc.w);
    STEP(0, xpA, tc.x);
    STEP(1, xpB, tc.y);
#undef STEP

    // Classifier head: lane holds h_final[p]; two full-warp reductions.
    float v0 = h * __ldg(W_fc + p);
    float v1 = h * __ldg(W_fc + HID + p);
#pragma unroll
    for (int o = 16; o > 0; o >>= 1) {
        v0 += __shfl_xor_sync(0xffffffffu, v0, o);
        v1 += __shfl_xor_sync(0xffffffffu, v1, o);
    }
    if (lane == 0) {
        out[b * NCLS + 0] = v0 + __ldg(b_fc + 0);
        out[b * NCLS + 1] = v1 + __ldg(b_fc + 1);
    }
}

extern "C" void kernel_launch(void* const* d_in, const int* in_sizes, int n_in,
                              void* d_out, int out_size) {
    const int*   x    = (const int*)d_in[0];
    const float* emb  = (const float*)d_in[1];
    const float* W_ih = (const float*)d_in[2];
    const float* W_hh = (const float*)d_in[3];
    const float* b_ih = (const float*)d_in[4];
    const float* b_hh = (const float*)d_in[5];
    const float* W_fc = (const float*)d_in[6];
    const float* b_fc = (const float*)d_in[7];
    float* out = (float*)d_out;

    build_proj_kernel<<<(VOCAB + 7) / 8, 256>>>(emb, W_ih, b_ih, b_hh);
    rnn_step_kernel<<<BATCH / 2, 64>>>(x, W_hh, W_fc, b_fc, out);
}